// round 14
// baseline (speedup 1.0000x reference)
#include <cuda_runtime.h>
#include <math.h>

#define NLOC 196
#define NPART 32
#define PI_F 3.14159265358979323846f
#define FPSCALE 1048576.0f          // 2^20
#define INV_FPSCALE (1.0f/1048576.0f)

// Globals (allocation-free rule). g_part slots are plain writes (owner-block),
// so NO zero-init and NO global atomics are needed.
__device__ unsigned long long g_part[NPART][NLOC];  // (sum<<32 | sumsq), both *2^20, per 16-batch slice
__device__ float4 g_W[81];   // z = W * (1,C0,S0)x(1,C1,S1)x(1,C2,S2)x(1,C3,S3)

// packed f32x2 fma (SASS FFMA2 — ptxas never auto-emits; PTX-only path)
#define FMA_F32X2(d, a, b, c) \
    asm("fma.rn.f32x2 %0, %1, %2, %3;" : "=l"(d) : "l"(a), "l"(b), "l"(c))
#define PACK_F32X2(out, lo, hi) \
    asm("mov.b64 %0, {%1, %2};" : "=l"(out) : "f"(lo), "f"(hi))
#define UNPACK_F32X2(lo, hi, in) \
    asm("mov.b64 {%0, %1}, %2;" : "=f"(lo), "=f"(hi) : "l"(in))

// spread bits of 4-bit x: bit i -> bit 2i
__device__ __forceinline__ int spread4(int x) {
    return (x & 1) | ((x & 2) << 1) | ((x & 4) << 2) | ((x & 8) << 3);
}

// One wire contraction of the pair-tensor: last base-4 digit (pair p=2k+k')
// -> base-3 digit m over (1, C, S) basis.
#define CSTEP(IN, OUT, NB, NM)                                         \
  do {                                                                 \
    const int cnt = (NB) * 3 * (NM);                                   \
    for (int e = tid; e < 4 * cnt; e += 256) {                         \
      int i = e / cnt; int o = e - i * cnt;                            \
      int M = o % (NM); int rest = o / (NM);                           \
      int m = rest % 3; int B = rest / 3;                              \
      float x0 = IN[i][(B * 4 + 0) * (NM) + M];                        \
      float x1 = IN[i][(B * 4 + 1) * (NM) + M];                        \
      float x2 = IN[i][(B * 4 + 2) * (NM) + M];                        \
      float x3 = IN[i][(B * 4 + 3) * (NM) + M];                        \
      float rV;                                                        \
      if (m == 0)      rV = 0.5f * (x0 + x3);                          \
      else if (m == 1) rV = 0.5f * (x0 - x3);                          \
      else             rV = 0.5f * (x1 + x2);                          \
      OUT[i][o] = rV;                                                  \
    }                                                                  \
    __syncthreads();                                                   \
  } while (0)

// ---------------------------------------------------------------------------
// K1: blocks 0..31 — stats partials over 16 batches each (coalesced float4
//     reads; packed int64 fixed-point smem atomics = order-independent exact
//     integer adds => deterministic; plain write to own g_part slot).
//     block 32 — build W (4 x 81) from params. Wire j <-> bit (3-j) of K.
// ---------------------------------------------------------------------------
__global__ void __launch_bounds__(256) qf_stats_w(const float* __restrict__ x,
                                                  const float* __restrict__ params) {
    const int tid = threadIdx.x;

    if (blockIdx.x < NPART) {
        __shared__ unsigned long long accP[NLOC];
        for (int e = tid; e < NLOC; e += 256) accP[e] = 0ULL;
        __syncthreads();

        // 16 batches = 3136 float4, all coalesced
        const float4* xs = reinterpret_cast<const float4*>(x) + blockIdx.x * 16 * 196;
        for (int i = tid; i < 3136; i += 256) {
            float4 v = xs[i];
            int idx4 = i % 196;                 // float4 index within its batch
            int off  = idx4 * 4;                // col-flat offset (one row)
            int row  = off / 28;
            int cq   = off - row * 28;
            int loc  = (row >> 1) * 14 + (cq >> 1);
            long long s0 = __float2ll_rn((v.x + v.y) * FPSCALE);
            long long q0 = __float2ll_rn((v.x * v.x + v.y * v.y) * FPSCALE);
            long long s1 = __float2ll_rn((v.z + v.w) * FPSCALE);
            long long q1 = __float2ll_rn((v.z * v.z + v.w * v.w) * FPSCALE);
            // 64 values/loc: |s|<2^29, q<2^31 => low-32 q never borrows into s
            atomicAdd(&accP[loc],     (unsigned long long)((s0 << 32) + q0));
            atomicAdd(&accP[loc + 1], (unsigned long long)((s1 << 32) + q1));
        }
        __syncthreads();

        for (int e = tid; e < NLOC; e += 256)
            g_part[blockIdx.x][e] = accP[e];    // plain write, slot owned
    } else {
        // ---- W build (shuffle-U + A + wire contraction) ----
        __shared__ float sP[16 * 17], sQ[16 * 17];
        __shared__ float bufA[4][256], bufB[4][256];
        {
            const int col = tid >> 4, K = tid & 15;
            float vr = (K == col) ? 1.f : 0.f, vi = 0.f;
            #pragma unroll
            for (int l = 0; l < 2; l++) {
                #pragma unroll
                for (int wi = 0; wi < 4; wi++) {   // RY(params[l][w][0])
                    float ss, cc; __sincosf(0.5f * params[(l * 4 + wi) * 3 + 0], &ss, &cc);
                    int m = 8 >> wi;
                    float orr = __shfl_xor_sync(0xffffffffu, vr, m);
                    float oii = __shfl_xor_sync(0xffffffffu, vi, m);
                    if (K & m) { vr = fmaf(ss, orr, cc * vr);  vi = fmaf(ss, oii, cc * vi); }
                    else       { vr = fmaf(-ss, orr, cc * vr); vi = fmaf(-ss, oii, cc * vi); }
                }
                #pragma unroll
                for (int i = 0; i < 3; i++) {      // CNOT(i -> i+1)
                    int cm = 8 >> i, tm = 8 >> (i + 1);
                    float orr = __shfl_xor_sync(0xffffffffu, vr, tm);
                    float oii = __shfl_xor_sync(0xffffffffu, vi, tm);
                    if (K & cm) { vr = orr; vi = oii; }
                }
                #pragma unroll
                for (int wi = 0; wi < 4; wi++) {   // RY(params[l][w][1])
                    float ss, cc; __sincosf(0.5f * params[(l * 4 + wi) * 3 + 1], &ss, &cc);
                    int m = 8 >> wi;
                    float orr = __shfl_xor_sync(0xffffffffu, vr, m);
                    float oii = __shfl_xor_sync(0xffffffffu, vi, m);
                    if (K & m) { vr = fmaf(ss, orr, cc * vr);  vi = fmaf(ss, oii, cc * vi); }
                    else       { vr = fmaf(-ss, orr, cc * vr); vi = fmaf(-ss, oii, cc * vi); }
                }
                #pragma unroll
                for (int i = 0; i < 3; i++) {      // CNOT(i+1 -> i)
                    int cm = 8 >> (i + 1), tm = 8 >> i;
                    float orr = __shfl_xor_sync(0xffffffffu, vr, tm);
                    float oii = __shfl_xor_sync(0xffffffffu, vi, tm);
                    if (K & cm) { vr = orr; vi = oii; }
                }
                #pragma unroll
                for (int wi = 0; wi < 4; wi++) {   // RZ(params[l][w][2])
                    float ss, cc; __sincosf(0.5f * params[(l * 4 + wi) * 3 + 2], &ss, &cc);
                    int m = 8 >> wi;
                    float rr = vr, ii = vi;
                    if (K & m) { vr = rr * cc - ii * ss; vi = ii * cc + rr * ss; }
                    else       { vr = rr * cc + ii * ss; vi = ii * cc - rr * ss; }
                }
            }
            sP[K * 17 + col] = vr;
            sQ[K * 17 + col] = vi;
        }
        __syncthreads();
        {
            const int k = tid >> 4, kp = tid & 15;
            float A0 = 0.f, A1 = 0.f, A2 = 0.f, A3 = 0.f;
            #pragma unroll
            for (int K = 0; K < 16; K++) {
                float pp = fmaf(sP[K * 17 + k], sP[K * 17 + kp],
                                sQ[K * 17 + k] * sQ[K * 17 + kp]);
                if (K & 8) A0 -= pp; else A0 += pp;
                if (K & 4) A1 -= pp; else A1 += pp;
                if (K & 2) A2 -= pp; else A2 += pp;
                if (K & 1) A3 -= pp; else A3 += pp;
            }
            int pi = 2 * spread4(k) + spread4(kp);
            bufA[0][pi] = A0; bufA[1][pi] = A1; bufA[2][pi] = A2; bufA[3][pi] = A3;
        }
        __syncthreads();
        CSTEP(bufA, bufB, 64, 1);
        CSTEP(bufB, bufA, 16, 3);
        CSTEP(bufA, bufB, 4, 9);
        CSTEP(bufB, bufA, 1, 27);
        if (tid < 81)
            g_W[tid] = make_float4(bufA[0][tid], bufA[1][tid], bufA[2][tid], bufA[3][tid]);
    }
}

// ---------------------------------------------------------------------------
// K2: one block per batch (512 blocks, 224 threads). Stage x[b] coalesced,
// load W as ulonglong2 pairs; thread p (<196): reduce the 32 stats partials
// (fixed order => deterministic), 4 full-angle __sincosf, then
// z = v01^T * M * v23 via packed fma.rn.f32x2 (FFMA2). Coalesced f4 output.
// ---------------------------------------------------------------------------
__global__ void __launch_bounds__(224) qf_eval(const float* __restrict__ x,
                                               float* __restrict__ out) {
    __shared__ float sx[784];
    __shared__ ulonglong2 sWk[81];   // same bits as float4 (pair-lo, pair-hi)
    const int tid = threadIdx.x;
    const int b = blockIdx.x;

    if (tid < 196)
        reinterpret_cast<float4*>(sx)[tid] = reinterpret_cast<const float4*>(x)[b * 196 + tid];
    if (tid < 81)
        sWk[tid] = reinterpret_cast<const ulonglong2*>(g_W)[tid];

    float mean = 0.f, scale = 0.f;
    if (tid < 196) {
        long long Sacc = 0, Qacc = 0;
        #pragma unroll 8
        for (int k = 0; k < NPART; k++) {
            unsigned long long P = g_part[k][tid];   // coalesced, L2-hot
            Sacc += (long long)(int)(P >> 32);
            Qacc += (long long)(P & 0xffffffffULL);
        }
        float S = (float)Sacc * INV_FPSCALE;
        float Q = (float)Qacc * INV_FPSCALE;
        mean = S * (1.f / 2048.f);
        float ssd = Q - S * S * (1.f / 2048.f);
        float sd  = sqrtf(ssd * (1.f / 2047.f));
        scale = __fdividef(PI_F, sd + 1e-8f);
    }
    __syncthreads();
    if (tid >= 196) return;

    const int r = tid / 14, c = tid - r * 14;
    float2 u  = *reinterpret_cast<float2*>(&sx[(2 * r) * 28 + 2 * c]);
    float2 w2 = *reinterpret_cast<float2*>(&sx[(2 * r + 1) * 28 + 2 * c]);

    float C0, S0, C1, S1, C2, S2, C3, S3;
    __sincosf((u.x  - mean) * scale, &S0, &C0);
    __sincosf((u.y  - mean) * scale, &S1, &C1);
    __sincosf((w2.x - mean) * scale, &S2, &C2);
    __sincosf((w2.y - mean) * scale, &S3, &C3);

    float v01[9];
    v01[0] = 1.f; v01[1] = C1;      v01[2] = S1;
    v01[3] = C0;  v01[4] = C0 * C1; v01[5] = C0 * S1;
    v01[6] = S0;  v01[7] = S0 * C1; v01[8] = S0 * S1;
    float v23[9];
    v23[0] = 1.f; v23[1] = C3;      v23[2] = S3;
    v23[3] = C2;  v23[4] = C2 * C3; v23[5] = C2 * S3;
    v23[6] = S2;  v23[7] = S2 * C3; v23[8] = S2 * S3;

    unsigned long long vb2[9];
    #pragma unroll
    for (int be = 0; be < 9; be++) PACK_F32X2(vb2[be], v23[be], v23[be]);

    unsigned long long z01 = 0ULL, z23 = 0ULL;   // packed (+0,+0)
    #pragma unroll
    for (int al = 0; al < 9; al++) {
        unsigned long long t01 = 0ULL, t23 = 0ULL;
        #pragma unroll
        for (int be = 0; be < 9; be++) {
            ulonglong2 wv = sWk[al * 9 + be];    // LDS.128 broadcast
            FMA_F32X2(t01, wv.x, vb2[be], t01);  // lanes (z0, z1)
            FMA_F32X2(t23, wv.y, vb2[be], t23);  // lanes (z2, z3)
        }
        unsigned long long ca2;
        PACK_F32X2(ca2, v01[al], v01[al]);
        FMA_F32X2(z01, t01, ca2, z01);
        FMA_F32X2(z23, t23, ca2, z23);
    }

    float z0, z1, z2, z3;
    UNPACK_F32X2(z0, z1, z01);
    UNPACK_F32X2(z2, z3, z23);

    // out row is location-major => contiguous per block, coalesced STG.128
    reinterpret_cast<float4*>(out)[b * 196 + tid] = make_float4(z0, z1, z2, z3);
}

extern "C" void kernel_launch(void* const* d_in, const int* in_sizes, int n_in,
                              void* d_out, int out_size) {
    const float* x      = (const float*)d_in[0];   // (512, 28, 28)
    const float* params = (const float*)d_in[1];   // (2, 4, 3)
    float* out          = (float*)d_out;           // (512, 784)

    qf_stats_w<<<NPART + 1, 256>>>(x, params);
    qf_eval<<<512, 224>>>(x, out);
}